// round 15
// baseline (speedup 1.0000x reference)
#include <cuda_runtime.h>
#include <cuda_bf16.h>
#include <cuda_fp16.h>
#include <cstdint>
#include <math.h>

#define NMAX   100000
#define EMAX   1000000
#define HDIM   64
#define NGRAPH 128
#define NCLS   5
#define NTILES ((NMAX + 127) / 128)     // 782

typedef unsigned long long u64;

// ---------------- scratch (device globals; never passed from host) ----------------
__device__ int    g_deg[NMAX];
__device__ int    g_cursor[NMAX];
__device__ int    g_off[NMAX + 1];
__device__ int    g_flag[128];
__device__ int    g_poolctr;
__device__ float  g_dinv[NMAX];
__device__ int    g_csrc[EMAX];
__device__ __align__(16) float  g_xs[NMAX * 2];
__device__ __align__(16) float4 g_ax4[NMAX];
__device__ __align__(16) unsigned char g_bf[(size_t)NTILES * 16384];   // t2 bf16, row-major 128-node tiles
__device__ __align__(16) unsigned char g_buf8[(size_t)NMAX * HDIM];    // g2s fp8 e4m3
__device__ __align__(16) float  g_h3[(size_t)NMAX * HDIM];
__device__ __align__(16) float  g_pooled[NGRAPH * HDIM];

// ---------------- helpers ----------------
__device__ __forceinline__ unsigned bf16pack(float lo, float hi) {
    unsigned r; asm("cvt.rn.bf16x2.f32 %0, %1, %2;" : "=r"(r) : "f"(hi), "f"(lo)); return r;
}
__device__ __forceinline__ unsigned short fp8pack2(float lo, float hi) {
    unsigned short r;
    asm("cvt.rn.satfinite.e4m3x2.f32 %0, %1, %2;" : "=h"(r) : "f"(hi), "f"(lo));
    return r;
}
__device__ __forceinline__ float2 fp8unpack2(unsigned short v) {
    unsigned h2;
    asm("cvt.rn.f16x2.e4m3x2 %0, %1;" : "=r"(h2) : "h"(v));
    return __half22float2(*(__half2*)&h2);
}
__device__ __forceinline__ uint32_t smem_u32(const void* p) {
    uint32_t a;
    asm("{ .reg .u64 t; cvta.to.shared.u64 t, %1; cvt.u32.u64 %0, t; }" : "=r"(a) : "l"(p));
    return a;
}
__device__ __forceinline__ float bf16resid(float x) {
    return x - __bfloat162float(__float2bfloat16(x));
}
__device__ __forceinline__ void mma_bf16(float* d, const unsigned* a, unsigned b0, unsigned b1) {
    asm volatile(
        "mma.sync.aligned.m16n8k16.row.col.f32.bf16.bf16.f32 "
        "{%0,%1,%2,%3}, {%4,%5,%6,%7}, {%8,%9}, {%0,%1,%2,%3};"
        : "+f"(d[0]), "+f"(d[1]), "+f"(d[2]), "+f"(d[3])
        : "r"(a[0]), "r"(a[1]), "r"(a[2]), "r"(a[3]), "r"(b0), "r"(b1));
}
__device__ __forceinline__ void ldmatrix4(unsigned* r, uint32_t addr) {
    asm volatile("ldmatrix.sync.aligned.m8n8.x4.shared.b16 {%0,%1,%2,%3}, [%4];"
        : "=r"(r[0]), "=r"(r[1]), "=r"(r[2]), "=r"(r[3]) : "r"(addr));
}

// ---------------- CSR build ----------------
__global__ void k_count4(const int* __restrict__ dst, int e) {
    if (blockIdx.x == 0 && threadIdx.x < 128) g_flag[threadIdx.x] = 0;
    int i4 = (blockIdx.x * blockDim.x + threadIdx.x) << 2;
    if (i4 >= e) return;
    if (i4 + 3 < e) {
        int4 d = *(const int4*)(dst + i4);
        atomicAdd(&g_deg[d.x], 1);
        atomicAdd(&g_deg[d.y], 1);
        atomicAdd(&g_deg[d.z], 1);
        atomicAdd(&g_deg[d.w], 1);
    } else {
        for (int i = i4; i < e; i++) atomicAdd(&g_deg[dst[i]], 1);
    }
}
__global__ void k_count1(const int* __restrict__ dst, int e) {
    if (blockIdx.x == 0 && threadIdx.x < 128) g_flag[threadIdx.x] = 0;
    int i = blockIdx.x * blockDim.x + threadIdx.x;
    if (i < e) atomicAdd(&g_deg[dst[i]], 1);
}

__global__ void k_scan(const float* __restrict__ x, int n) {
    int b = blockIdx.x;
    int i = (b << 10) + threadIdx.x;
    int v = (i < n) ? g_deg[i] : 0;
    float dv = rsqrtf((float)(v + 1));
    if (i < n) {
        g_deg[i] = 0;
        g_dinv[i] = dv;
        float2 xv = *(const float2*)(x + 2 * i);
        g_xs[2 * i]     = dv * xv.x;
        g_xs[2 * i + 1] = dv * xv.y;
    }
    int lane = threadIdx.x & 31, wid = threadIdx.x >> 5;
    int xacc = v;
    #pragma unroll
    for (int o = 1; o < 32; o <<= 1) {
        int y = __shfl_up_sync(0xffffffffu, xacc, o);
        if (lane >= o) xacc += y;
    }
    __shared__ int ws[32];
    __shared__ int s_prefix;
    if (lane == 31) ws[wid] = xacc;
    __syncthreads();
    if (wid == 0) {
        int s = ws[lane];
        #pragma unroll
        for (int o = 1; o < 32; o <<= 1) {
            int y = __shfl_up_sync(0xffffffffu, s, o);
            if (lane >= o) s += y;
        }
        ws[lane] = s;
    }
    __syncthreads();
    int warpoff = (wid == 0) ? 0 : ws[wid - 1];
    int total = ws[31];
    if (threadIdx.x == 0) atomicExch(&g_flag[b], (int)(0x80000000u | (unsigned)total));
    if (threadIdx.x < 32) {
        int sum = 0;
        for (int p = b - 1 - (int)threadIdx.x; p >= 0; p -= 32) {
            int f;
            do { f = atomicAdd(&g_flag[p], 0); } while (f >= 0);
            sum += f & 0x7fffffff;
        }
        #pragma unroll
        for (int o = 16; o; o >>= 1) sum += __shfl_xor_sync(0xffffffffu, sum, o);
        if (threadIdx.x == 0) s_prefix = sum;
    }
    __syncthreads();
    if (i < n) {
        int off = s_prefix + warpoff + xacc - v;
        g_off[i] = off;
        g_cursor[i] = off;
        if (i == n - 1) g_off[n] = s_prefix + warpoff + xacc;
    }
}

__global__ void k_scatter4(const int* __restrict__ ei, int e) {
    int i4 = (blockIdx.x * blockDim.x + threadIdx.x) << 2;
    if (i4 >= e) return;
    if (i4 + 3 < e) {
        int4 s = *(const int4*)(ei + i4);
        int4 d = *(const int4*)(ei + e + i4);
        int p0 = atomicAdd(&g_cursor[d.x], 1);
        int p1 = atomicAdd(&g_cursor[d.y], 1);
        int p2 = atomicAdd(&g_cursor[d.z], 1);
        int p3 = atomicAdd(&g_cursor[d.w], 1);
        g_csrc[p0] = s.x; g_csrc[p1] = s.y;
        g_csrc[p2] = s.z; g_csrc[p3] = s.w;
    } else {
        for (int i = i4; i < e; i++) {
            int s = ei[i], d = ei[e + i];
            int p = atomicAdd(&g_cursor[d], 1);
            g_csrc[p] = s;
        }
    }
}
__global__ void k_scatter1(const int* __restrict__ ei, int e) {
    int i = blockIdx.x * blockDim.x + threadIdx.x;
    if (i >= e) return;
    int s = ei[i], d = ei[e + i];
    int p = atomicAdd(&g_cursor[d], 1);
    g_csrc[p] = s;
}

// ---------------- layer 1: 2 threads/node (even/odd edge streams) ----------------
__global__ void k_agg2(int n) {
    int idx = blockIdx.x * blockDim.x + threadIdx.x;
    int v = idx >> 1, sub = idx & 1;
    if (v >= n) return;
    int st = g_off[v], en = g_off[v + 1];
    float ax = 0.f, ay = 0.f;
    for (int j = st + sub; j < en; j += 8) {
        // edges j, j+2, j+4, j+6 (this thread's stream)
        int rem = en - j;
        int s0 = __ldg(&g_csrc[j]);
        int s1 = (rem > 2) ? __ldg(&g_csrc[j + 2]) : s0;
        int s2 = (rem > 4) ? __ldg(&g_csrc[j + 4]) : s0;
        int s3 = (rem > 6) ? __ldg(&g_csrc[j + 6]) : s0;
        float2 x0 = *(const float2*)(g_xs + 2 * s0);
        float2 x1 = *(const float2*)(g_xs + 2 * s1);
        float2 x2 = *(const float2*)(g_xs + 2 * s2);
        float2 x3 = *(const float2*)(g_xs + 2 * s3);
        float m1 = (rem > 2) ? 1.f : 0.f;
        float m2 = (rem > 4) ? 1.f : 0.f;
        float m3 = (rem > 6) ? 1.f : 0.f;
        ax += x0.x; ay += x0.y;
        ax = fmaf(m1, x1.x, ax); ay = fmaf(m1, x1.y, ay);
        ax = fmaf(m2, x2.x, ax); ay = fmaf(m2, x2.y, ay);
        ax = fmaf(m3, x3.x, ax); ay = fmaf(m3, x3.y, ay);
    }
    ax += __shfl_xor_sync(0xffffffffu, ax, 1);
    ay += __shfl_xor_sync(0xffffffffu, ay, 1);
    if (sub == 0) {
        float dv = g_dinv[v];
        ax += g_xs[2 * v];
        ay += g_xs[2 * v + 1];
        float4 o; o.x = dv * ax; o.y = dv * ay; o.z = dv; o.w = 0.f;
        g_ax4[v] = o;
    }
}

// ---------------- layer 2 agg + lin1 -> bf16 row-major tiles ----------------
__global__ void k_l2agg(const float* __restrict__ W1, const float* __restrict__ b1, int n) {
    __shared__ float sT[64 * 9];
    int t = threadIdx.x, wid = t >> 5, lane = t & 31;
    int v = blockIdx.x * 8 + wid;
    float w1x0 = W1[lane],      w1y0 = W1[64 + lane],  bb0 = b1[lane];
    float w1x1 = W1[lane + 32], w1y1 = W1[96 + lane],  bb1 = b1[lane + 32];
    float a0 = 0.f, a1 = 0.f;
    if (v < n) {
        int st = g_off[v], en = g_off[v + 1];
        for (int j = st; j < en; j += 4) {
            int rem = en - j;
            int s0 = __ldg(&g_csrc[j]);
            int s1 = (rem > 1) ? __ldg(&g_csrc[j + 1]) : s0;
            int s2 = (rem > 2) ? __ldg(&g_csrc[j + 2]) : s0;
            int s3 = (rem > 3) ? __ldg(&g_csrc[j + 3]) : s0;
            float4 q0 = g_ax4[s0];
            float4 q1 = g_ax4[s1];
            float4 q2 = g_ax4[s2];
            float4 q3 = g_ax4[s3];
            float m1 = (rem > 1) ? 1.f : 0.f;
            float m2 = (rem > 2) ? 1.f : 0.f;
            float m3 = (rem > 3) ? 1.f : 0.f;
            float h;
            h = fmaxf(fmaf(q0.x, w1x0, fmaf(q0.y, w1y0, bb0)), 0.f); a0 = fmaf(q0.z, h, a0);
            h = fmaxf(fmaf(q0.x, w1x1, fmaf(q0.y, w1y1, bb1)), 0.f); a1 = fmaf(q0.z, h, a1);
            h = fmaxf(fmaf(q1.x, w1x0, fmaf(q1.y, w1y0, bb0)), 0.f); a0 = fmaf(m1 * q1.z, h, a0);
            h = fmaxf(fmaf(q1.x, w1x1, fmaf(q1.y, w1y1, bb1)), 0.f); a1 = fmaf(m1 * q1.z, h, a1);
            h = fmaxf(fmaf(q2.x, w1x0, fmaf(q2.y, w1y0, bb0)), 0.f); a0 = fmaf(m2 * q2.z, h, a0);
            h = fmaxf(fmaf(q2.x, w1x1, fmaf(q2.y, w1y1, bb1)), 0.f); a1 = fmaf(m2 * q2.z, h, a1);
            h = fmaxf(fmaf(q3.x, w1x0, fmaf(q3.y, w1y0, bb0)), 0.f); a0 = fmaf(m3 * q3.z, h, a0);
            h = fmaxf(fmaf(q3.x, w1x1, fmaf(q3.y, w1y1, bb1)), 0.f); a1 = fmaf(m3 * q3.z, h, a1);
        }
        float4 q = g_ax4[v];
        float h;
        h = fmaxf(fmaf(q.x, w1x0, fmaf(q.y, w1y0, bb0)), 0.f); a0 = fmaf(q.z, h, a0);
        h = fmaxf(fmaf(q.x, w1x1, fmaf(q.y, w1y1, bb1)), 0.f); a1 = fmaf(q.z, h, a1);
        a0 *= q.z;
        a1 *= q.z;
    }
    sT[lane * 9 + wid] = a0;
    sT[(lane + 32) * 9 + wid] = a1;
    __syncthreads();
    if (t < 64) {
        int j = t >> 3, ch = t & 7;
        int v2 = blockIdx.x * 8 + j;
        if (v2 < n) {
            int tile = v2 >> 7, r = v2 & 127;
            uint4 u;
            u.x = bf16pack(sT[(ch*8+0)*9 + j], sT[(ch*8+1)*9 + j]);
            u.y = bf16pack(sT[(ch*8+2)*9 + j], sT[(ch*8+3)*9 + j]);
            u.z = bf16pack(sT[(ch*8+4)*9 + j], sT[(ch*8+5)*9 + j]);
            u.w = bf16pack(sT[(ch*8+6)*9 + j], sT[(ch*8+7)*9 + j]);
            *(uint4*)(g_bf + (size_t)tile * 16384 + r * 128 + ch * 16) = u;
        }
    }
}

// ---------------- mma.sync MLP (R14-validated) ----------------
__global__ __launch_bounds__(256, 2) void k_mlp(const float* __restrict__ W2,
                                                const float* __restrict__ b2,
                                                const float* __restrict__ W3,
                                                int n) {
    extern __shared__ char sm[];
    u64*  bfr = (u64*)sm;                  // [4][4][8][32] weight fragments, 32KB
    char* At  = sm + 32768;                // A tile: 128 x 144B
    const int t = threadIdx.x, lane = t & 31, w = t >> 5;

    for (int fg = w; fg < 128; fg += 8) {
        int v  = fg >> 5;
        int ks = (fg >> 3) & 3;
        int nb = fg & 7;
        const float* W = (v < 2) ? W2 : W3;
        int nn = nb * 8 + (lane >> 2);
        int k0 = ks * 16 + (lane & 3) * 2;
        float w00 = __ldg(&W[k0 * 64 + nn]);
        float w01 = __ldg(&W[(k0 + 1) * 64 + nn]);
        float w08 = __ldg(&W[(k0 + 8) * 64 + nn]);
        float w09 = __ldg(&W[(k0 + 9) * 64 + nn]);
        unsigned b0, b1;
        if (v & 1) {
            b0 = bf16pack(bf16resid(w00), bf16resid(w01));
            b1 = bf16pack(bf16resid(w08), bf16resid(w09));
        } else {
            b0 = bf16pack(w00, w01);
            b1 = bf16pack(w08, w09);
        }
        bfr[fg * 32 + lane] = ((u64)b1 << 32) | (u64)b0;
    }
    float2 b2p[8];
    #pragma unroll
    for (int nb = 0; nb < 8; nb++) {
        int c = nb * 8 + (lane & 3) * 2;
        b2p[nb] = make_float2(__ldg(&b2[c]), __ldg(&b2[c + 1]));
    }
    __syncthreads();

    const uint32_t at_base = smem_u32(At);
    const int ntiles = (n + 127) >> 7;
    for (int tile = blockIdx.x; tile < ntiles; tile += gridDim.x) {
        const int base = tile << 7;
        for (int q = t; q < 1024; q += 256) {
            int r = q >> 3, p = q & 7;
            uint4 val = *(const uint4*)(g_bf + (size_t)tile * 16384 + r * 128 + p * 16);
            *(uint4*)(At + r * 144 + p * 16) = val;
        }
        __syncthreads();

        unsigned aF[4][4];
        uint32_t arow = at_base + (w * 16 + (lane & 15)) * 144 + (lane >> 4) * 16;
        #pragma unroll
        for (int ks = 0; ks < 4; ks++) ldmatrix4(aF[ks], arow + ks * 32);
        __syncthreads();

        float acc[8][4];
        #pragma unroll
        for (int nb = 0; nb < 8; nb++)
            #pragma unroll
            for (int i = 0; i < 4; i++) acc[nb][i] = 0.f;
        #pragma unroll
        for (int ks = 0; ks < 4; ks++) {
            #pragma unroll
            for (int nb = 0; nb < 8; nb++) {
                u64 fh = bfr[((0 * 4 + ks) * 8 + nb) * 32 + lane];
                mma_bf16(acc[nb], aF[ks], (unsigned)fh, (unsigned)(fh >> 32));
                u64 fl = bfr[((1 * 4 + ks) * 8 + nb) * 32 + lane];
                mma_bf16(acc[nb], aF[ks], (unsigned)fl, (unsigned)(fl >> 32));
            }
        }

        unsigned a2[4][4];
        #pragma unroll
        for (int j = 0; j < 4; j++) {
            int n0 = 2 * j, n1 = 2 * j + 1;
            a2[j][0] = bf16pack(fmaxf(acc[n0][0] + b2p[n0].x, 0.f),
                                fmaxf(acc[n0][1] + b2p[n0].y, 0.f));
            a2[j][1] = bf16pack(fmaxf(acc[n0][2] + b2p[n0].x, 0.f),
                                fmaxf(acc[n0][3] + b2p[n0].y, 0.f));
            a2[j][2] = bf16pack(fmaxf(acc[n1][0] + b2p[n1].x, 0.f),
                                fmaxf(acc[n1][1] + b2p[n1].y, 0.f));
            a2[j][3] = bf16pack(fmaxf(acc[n1][2] + b2p[n1].x, 0.f),
                                fmaxf(acc[n1][3] + b2p[n1].y, 0.f));
        }

        float acc2[8][4];
        #pragma unroll
        for (int nb = 0; nb < 8; nb++)
            #pragma unroll
            for (int i = 0; i < 4; i++) acc2[nb][i] = 0.f;
        #pragma unroll
        for (int ks = 0; ks < 4; ks++) {
            #pragma unroll
            for (int nb = 0; nb < 8; nb++) {
                u64 fh = bfr[((2 * 4 + ks) * 8 + nb) * 32 + lane];
                mma_bf16(acc2[nb], a2[ks], (unsigned)fh, (unsigned)(fh >> 32));
                u64 fl = bfr[((3 * 4 + ks) * 8 + nb) * 32 + lane];
                mma_bf16(acc2[nb], a2[ks], (unsigned)fl, (unsigned)(fl >> 32));
            }
        }

        int r0 = base + w * 16 + (lane >> 2);
        int r1 = r0 + 8;
        float dv0 = (r0 < n) ? __ldg(&g_dinv[r0]) : 0.f;
        float dv1 = (r1 < n) ? __ldg(&g_dinv[r1]) : 0.f;
        int coff = (lane & 3) * 2;
        #pragma unroll
        for (int nb = 0; nb < 8; nb++) {
            unsigned short v0 = fp8pack2(acc2[nb][0] * dv0, acc2[nb][1] * dv0);
            unsigned short v1 = fp8pack2(acc2[nb][2] * dv1, acc2[nb][3] * dv1);
            if (r0 < n) *(unsigned short*)(g_buf8 + (size_t)r0 * 64 + nb * 8 + coff) = v0;
            if (r1 < n) *(unsigned short*)(g_buf8 + (size_t)r1 * 64 + nb * 8 + coff) = v1;
        }
    }
}

// ---------------- layer 3 aggregation: 2 edges/iter per half-warp (MLP 4) --------
__global__ void k_agg64(const float* __restrict__ b3, int n) {
    int t = threadIdx.x;
    int w = (blockIdx.x * blockDim.x + t) >> 5;
    int lane = t & 31;
    int half = lane >> 4, l16 = lane & 15;
    if (w >= n) return;
    int st = g_off[w], en = g_off[w + 1];
    float4 a = make_float4(0.f, 0.f, 0.f, 0.f);
    int j = st + half;
    int s0 = (j < en) ? __ldg(&g_csrc[j]) : 0;
    int s1 = (j + 2 < en) ? __ldg(&g_csrc[j + 2]) : 0;
    while (j < en) {
        int s2 = (j + 4 < en) ? __ldg(&g_csrc[j + 4]) : 0;
        int s3 = (j + 6 < en) ? __ldg(&g_csrc[j + 6]) : 0;
        unsigned u0 = *(const unsigned*)(g_buf8 + (size_t)s0 * 64 + l16 * 4);
        if (j + 2 < en) {
            unsigned u1 = *(const unsigned*)(g_buf8 + (size_t)s1 * 64 + l16 * 4);
            float2 g01 = fp8unpack2((unsigned short)(u1 & 0xffffu));
            float2 g23 = fp8unpack2((unsigned short)(u1 >> 16));
            a.x += g01.x; a.y += g01.y; a.z += g23.x; a.w += g23.y;
        }
        float2 f01 = fp8unpack2((unsigned short)(u0 & 0xffffu));
        float2 f23 = fp8unpack2((unsigned short)(u0 >> 16));
        a.x += f01.x; a.y += f01.y; a.z += f23.x; a.w += f23.y;
        j += 4; s0 = s2; s1 = s3;
    }
    if (half == 0) {
        unsigned u = *(const unsigned*)(g_buf8 + (size_t)w * 64 + l16 * 4);   // self
        float2 f01 = fp8unpack2((unsigned short)(u & 0xffffu));
        float2 f23 = fp8unpack2((unsigned short)(u >> 16));
        a.x += f01.x; a.y += f01.y; a.z += f23.x; a.w += f23.y;
    }
    a.x += __shfl_xor_sync(0xffffffffu, a.x, 16);
    a.y += __shfl_xor_sync(0xffffffffu, a.y, 16);
    a.z += __shfl_xor_sync(0xffffffffu, a.z, 16);
    a.w += __shfl_xor_sync(0xffffffffu, a.w, 16);
    if (half == 0) {
        float dv = g_dinv[w];
        float4 bb = *(const float4*)(b3 + l16 * 4);
        a.x = fmaf(dv, a.x, bb.x); a.y = fmaf(dv, a.y, bb.y);
        a.z = fmaf(dv, a.z, bb.z); a.w = fmaf(dv, a.w, bb.w);
        *(float4*)(g_h3 + (size_t)w * 64 + l16 * 4) = a;
    }
}

// ---------------- mean pool + head ----------------
__global__ void k_poolfinal(const int* __restrict__ batch, const float* __restrict__ ge,
                            const float* __restrict__ Wl, const float* __restrict__ bl,
                            float* __restrict__ out, int n) {
    __shared__ int sb[2];
    __shared__ float red[256];
    __shared__ int s_last;
    int gid = blockIdx.x;
    int t = threadIdx.x;
    if (t < 2) {
        int target = gid + t;
        int lo = 0, hi = n;
        while (lo < hi) {
            int mid = (lo + hi) >> 1;
            if (batch[mid] < target) lo = mid + 1; else hi = mid;
        }
        sb[t] = lo;
    }
    __syncthreads();
    int s = sb[0], e = sb[1];
    int d = t & 63, str = t >> 6;
    float acc = 0.f;
    for (int nn = s + str; nn < e; nn += 4) acc += g_h3[(size_t)nn * 64 + d];
    red[t] = acc;
    __syncthreads();
    if (t < 64) {
        float tot = red[t] + red[t + 64] + red[t + 128] + red[t + 192];
        g_pooled[gid * 64 + t] = tot / fmaxf((float)(e - s), 1.f);
    }
    __threadfence();
    if (t == 0) s_last = (atomicAdd(&g_poolctr, 1) == NGRAPH - 1);
    __syncthreads();
    if (!s_last) return;

    if (t == 0) g_poolctr = 0;
    __shared__ float sW[128 * NCLS];
    __shared__ float sbv[NCLS];
    for (int i = t; i < 128 * NCLS; i += 256) sW[i] = Wl[i];
    if (t < NCLS) sbv[t] = bl[t];
    __syncthreads();
    if (t < 128) {
        int g = t;
        float z[NCLS];
        #pragma unroll
        for (int c = 0; c < NCLS; c++) z[c] = sbv[c];
        for (int k = 0; k < 64; k++) {
            float p = g_pooled[g * HDIM + k];
            #pragma unroll
            for (int c = 0; c < NCLS; c++) z[c] = fmaf(p, sW[k * NCLS + c], z[c]);
        }
        for (int k = 0; k < 64; k++) {
            float p = ge[g * 64 + k];
            #pragma unroll
            for (int c = 0; c < NCLS; c++) z[c] = fmaf(p, sW[(64 + k) * NCLS + c], z[c]);
        }
        float m = z[0];
        #pragma unroll
        for (int c = 1; c < NCLS; c++) m = fmaxf(m, z[c]);
        float sum = 0.f;
        #pragma unroll
        for (int c = 0; c < NCLS; c++) sum += expf(z[c] - m);
        float l = m + logf(sum);
        #pragma unroll
        for (int c = 0; c < NCLS; c++) out[g * NCLS + c] = z[c] - l;
    }
}

// ---------------- launch ----------------
extern "C" void kernel_launch(void* const* d_in, const int* in_sizes, int n_in,
                              void* d_out, int out_size) {
    const float* x     = (const float*)d_in[0];
    const int*   ei    = (const int*)d_in[1];
    const int*   batch = (const int*)d_in[2];
    const float* ge    = (const float*)d_in[3];
    const float* W1    = (const float*)d_in[4];
    const float* b1    = (const float*)d_in[5];
    const float* W2    = (const float*)d_in[6];
    const float* b2    = (const float*)d_in[7];
    const float* W3    = (const float*)d_in[8];
    const float* b3    = (const float*)d_in[9];
    const float* Wl    = (const float*)d_in[10];
    const float* bl    = (const float*)d_in[11];
    float* out = (float*)d_out;

    int n  = in_sizes[0] / 2;
    int e  = in_sizes[1] / 2;
    int nb = (n + 1023) / 1024;

    static const int mlp_smem = 32768 + 128 * 144;   // 51200 B
    cudaFuncSetAttribute(k_mlp, cudaFuncAttributeMaxDynamicSharedMemorySize, mlp_smem);

    if ((e & 3) == 0)
        k_count4<<<((e >> 2) + 255) / 256, 256>>>(ei + e, e);    // 0
    else
        k_count1<<<(e + 255) / 256, 256>>>(ei + e, e);
    k_scan   <<<nb, 1024>>>(x, n);                               // 1
    if ((e & 3) == 0)
        k_scatter4<<<((e >> 2) + 255) / 256, 256>>>(ei, e);      // 2
    else
        k_scatter1<<<(e + 255) / 256, 256>>>(ei, e);
    k_agg2   <<<(2 * n + 255) / 256, 256>>>(n);                  // 3  (2 thr/node)
    k_l2agg  <<<(n + 7) / 8, 256>>>(W1, b1, n);                  // 4
    k_mlp    <<<296, 256, mlp_smem>>>(W2, b2, W3, n);            // 5
    k_agg64  <<<(n + 7) / 8, 256>>>(b3, n);                      // 6
    k_poolfinal<<<NGRAPH, 256>>>(batch, ge, Wl, bl, out, n);     // 7
}

// round 17
// speedup vs baseline: 1.0160x; 1.0160x over previous
#include <cuda_runtime.h>
#include <cuda_bf16.h>
#include <cuda_fp16.h>
#include <cstdint>
#include <math.h>

#define NMAX   100000
#define EMAX   1000000
#define HDIM   64
#define NGRAPH 128
#define NCLS   5
#define NTILES ((NMAX + 127) / 128)     // 782

typedef unsigned long long u64;

// ---------------- scratch (device globals; never passed from host) ----------------
__device__ int    g_deg[NMAX];
__device__ int    g_cursor[NMAX];
__device__ int    g_off[NMAX + 1];
__device__ int    g_flag[128];
__device__ int    g_poolctr;
__device__ float  g_dinv[NMAX];
__device__ int    g_csrc[EMAX];
__device__ __align__(16) float  g_xs[NMAX * 2];
__device__ __align__(16) float4 g_ax4[NMAX];
__device__ __align__(16) unsigned char g_bf[(size_t)NTILES * 16384];   // t2 bf16, row-major 128-node tiles
__device__ __align__(16) unsigned char g_buf8[(size_t)NMAX * HDIM];    // g2s fp8 e4m3
__device__ __align__(16) float  g_h3[(size_t)NMAX * HDIM];
__device__ __align__(16) float  g_pooled[NGRAPH * HDIM];

// ---------------- helpers ----------------
__device__ __forceinline__ unsigned bf16pack(float lo, float hi) {
    unsigned r; asm("cvt.rn.bf16x2.f32 %0, %1, %2;" : "=r"(r) : "f"(hi), "f"(lo)); return r;
}
__device__ __forceinline__ unsigned short fp8pack2(float lo, float hi) {
    unsigned short r;
    asm("cvt.rn.satfinite.e4m3x2.f32 %0, %1, %2;" : "=h"(r) : "f"(hi), "f"(lo));
    return r;
}
__device__ __forceinline__ float2 fp8unpack2(unsigned short v) {
    unsigned h2;
    asm("cvt.rn.f16x2.e4m3x2 %0, %1;" : "=r"(h2) : "h"(v));
    return __half22float2(*(__half2*)&h2);
}
__device__ __forceinline__ uint32_t smem_u32(const void* p) {
    uint32_t a;
    asm("{ .reg .u64 t; cvta.to.shared.u64 t, %1; cvt.u32.u64 %0, t; }" : "=r"(a) : "l"(p));
    return a;
}
__device__ __forceinline__ float bf16resid(float x) {
    return x - __bfloat162float(__float2bfloat16(x));
}
__device__ __forceinline__ void mma_bf16(float* d, const unsigned* a, unsigned b0, unsigned b1) {
    asm volatile(
        "mma.sync.aligned.m16n8k16.row.col.f32.bf16.bf16.f32 "
        "{%0,%1,%2,%3}, {%4,%5,%6,%7}, {%8,%9}, {%0,%1,%2,%3};"
        : "+f"(d[0]), "+f"(d[1]), "+f"(d[2]), "+f"(d[3])
        : "r"(a[0]), "r"(a[1]), "r"(a[2]), "r"(a[3]), "r"(b0), "r"(b1));
}
__device__ __forceinline__ void ldmatrix4(unsigned* r, uint32_t addr) {
    asm volatile("ldmatrix.sync.aligned.m8n8.x4.shared.b16 {%0,%1,%2,%3}, [%4];"
        : "=r"(r[0]), "=r"(r[1]), "=r"(r[2]), "=r"(r[3]) : "r"(addr));
}

// ---------------- CSR build ----------------
__global__ void k_count4(const int* __restrict__ dst, int e) {
    if (blockIdx.x == 0 && threadIdx.x < 128) g_flag[threadIdx.x] = 0;
    int i4 = (blockIdx.x * blockDim.x + threadIdx.x) << 2;
    if (i4 >= e) return;
    if (i4 + 3 < e) {
        int4 d = *(const int4*)(dst + i4);
        atomicAdd(&g_deg[d.x], 1);
        atomicAdd(&g_deg[d.y], 1);
        atomicAdd(&g_deg[d.z], 1);
        atomicAdd(&g_deg[d.w], 1);
    } else {
        for (int i = i4; i < e; i++) atomicAdd(&g_deg[dst[i]], 1);
    }
}
__global__ void k_count1(const int* __restrict__ dst, int e) {
    if (blockIdx.x == 0 && threadIdx.x < 128) g_flag[threadIdx.x] = 0;
    int i = blockIdx.x * blockDim.x + threadIdx.x;
    if (i < e) atomicAdd(&g_deg[dst[i]], 1);
}

__global__ void k_scan(const float* __restrict__ x, int n) {
    int b = blockIdx.x;
    int i = (b << 10) + threadIdx.x;
    int v = (i < n) ? g_deg[i] : 0;
    float dv = rsqrtf((float)(v + 1));
    if (i < n) {
        g_deg[i] = 0;
        g_dinv[i] = dv;
        float2 xv = *(const float2*)(x + 2 * i);
        g_xs[2 * i]     = dv * xv.x;
        g_xs[2 * i + 1] = dv * xv.y;
    }
    int lane = threadIdx.x & 31, wid = threadIdx.x >> 5;
    int xacc = v;
    #pragma unroll
    for (int o = 1; o < 32; o <<= 1) {
        int y = __shfl_up_sync(0xffffffffu, xacc, o);
        if (lane >= o) xacc += y;
    }
    __shared__ int ws[32];
    __shared__ int s_prefix;
    if (lane == 31) ws[wid] = xacc;
    __syncthreads();
    if (wid == 0) {
        int s = ws[lane];
        #pragma unroll
        for (int o = 1; o < 32; o <<= 1) {
            int y = __shfl_up_sync(0xffffffffu, s, o);
            if (lane >= o) s += y;
        }
        ws[lane] = s;
    }
    __syncthreads();
    int warpoff = (wid == 0) ? 0 : ws[wid - 1];
    int total = ws[31];
    if (threadIdx.x == 0) atomicExch(&g_flag[b], (int)(0x80000000u | (unsigned)total));
    if (threadIdx.x < 32) {
        int sum = 0;
        for (int p = b - 1 - (int)threadIdx.x; p >= 0; p -= 32) {
            int f;
            do { f = atomicAdd(&g_flag[p], 0); } while (f >= 0);
            sum += f & 0x7fffffff;
        }
        #pragma unroll
        for (int o = 16; o; o >>= 1) sum += __shfl_xor_sync(0xffffffffu, sum, o);
        if (threadIdx.x == 0) s_prefix = sum;
    }
    __syncthreads();
    if (i < n) {
        int off = s_prefix + warpoff + xacc - v;
        g_off[i] = off;
        g_cursor[i] = off;
        if (i == n - 1) g_off[n] = s_prefix + warpoff + xacc;
    }
}

__global__ void k_scatter4(const int* __restrict__ ei, int e) {
    int i4 = (blockIdx.x * blockDim.x + threadIdx.x) << 2;
    if (i4 >= e) return;
    if (i4 + 3 < e) {
        int4 s = *(const int4*)(ei + i4);
        int4 d = *(const int4*)(ei + e + i4);
        int p0 = atomicAdd(&g_cursor[d.x], 1);
        int p1 = atomicAdd(&g_cursor[d.y], 1);
        int p2 = atomicAdd(&g_cursor[d.z], 1);
        int p3 = atomicAdd(&g_cursor[d.w], 1);
        g_csrc[p0] = s.x; g_csrc[p1] = s.y;
        g_csrc[p2] = s.z; g_csrc[p3] = s.w;
    } else {
        for (int i = i4; i < e; i++) {
            int s = ei[i], d = ei[e + i];
            int p = atomicAdd(&g_cursor[d], 1);
            g_csrc[p] = s;
        }
    }
}
__global__ void k_scatter1(const int* __restrict__ ei, int e) {
    int i = blockIdx.x * blockDim.x + threadIdx.x;
    if (i >= e) return;
    int s = ei[i], d = ei[e + i];
    int p = atomicAdd(&g_cursor[d], 1);
    g_csrc[p] = s;
}

// ---------------- layer 1: 2 threads/node (even/odd edge streams) ----------------
__global__ void k_agg2(int n) {
    int idx = blockIdx.x * blockDim.x + threadIdx.x;
    int v = idx >> 1, sub = idx & 1;
    if (v >= n) return;
    int st = g_off[v], en = g_off[v + 1];
    float ax = 0.f, ay = 0.f;
    for (int j = st + sub; j < en; j += 8) {
        int rem = en - j;
        int s0 = __ldg(&g_csrc[j]);
        int s1 = (rem > 2) ? __ldg(&g_csrc[j + 2]) : s0;
        int s2 = (rem > 4) ? __ldg(&g_csrc[j + 4]) : s0;
        int s3 = (rem > 6) ? __ldg(&g_csrc[j + 6]) : s0;
        float2 x0 = *(const float2*)(g_xs + 2 * s0);
        float2 x1 = *(const float2*)(g_xs + 2 * s1);
        float2 x2 = *(const float2*)(g_xs + 2 * s2);
        float2 x3 = *(const float2*)(g_xs + 2 * s3);
        float m1 = (rem > 2) ? 1.f : 0.f;
        float m2 = (rem > 4) ? 1.f : 0.f;
        float m3 = (rem > 6) ? 1.f : 0.f;
        ax += x0.x; ay += x0.y;
        ax = fmaf(m1, x1.x, ax); ay = fmaf(m1, x1.y, ay);
        ax = fmaf(m2, x2.x, ax); ay = fmaf(m2, x2.y, ay);
        ax = fmaf(m3, x3.x, ax); ay = fmaf(m3, x3.y, ay);
    }
    ax += __shfl_xor_sync(0xffffffffu, ax, 1);
    ay += __shfl_xor_sync(0xffffffffu, ay, 1);
    if (sub == 0) {
        float dv = g_dinv[v];
        ax += g_xs[2 * v];
        ay += g_xs[2 * v + 1];
        float4 o; o.x = dv * ax; o.y = dv * ay; o.z = dv; o.w = 0.f;
        g_ax4[v] = o;
    }
}

// ---------------- layer 2 agg + lin1 -> bf16 row-major tiles ----------------
// warp per node; adjacency indices prefetched lane-parallel (1 coalesced load),
// broadcast via shfl (warp-uniform loop) -> independent feature gathers.
__global__ void k_l2agg(const float* __restrict__ W1, const float* __restrict__ b1, int n) {
    __shared__ float sT[64 * 9];
    int t = threadIdx.x, wid = t >> 5, lane = t & 31;
    int v = blockIdx.x * 8 + wid;
    float w1x0 = W1[lane],      w1y0 = W1[64 + lane],  bb0 = b1[lane];
    float w1x1 = W1[lane + 32], w1y1 = W1[96 + lane],  bb1 = b1[lane + 32];
    float a0 = 0.f, a1 = 0.f;
    if (v < n) {
        int st = g_off[v];
        int deg = g_off[v + 1] - st;
        for (int base = 0; base < deg; base += 32) {
            int li = base + lane;
            int myidx = (li < deg) ? __ldg(&g_csrc[st + li]) : 0;
            int cnt = min(32, deg - base);
            int e = 0;
            for (; e + 3 < cnt; e += 4) {
                int s0 = __shfl_sync(0xffffffffu, myidx, e);
                int s1 = __shfl_sync(0xffffffffu, myidx, e + 1);
                int s2 = __shfl_sync(0xffffffffu, myidx, e + 2);
                int s3 = __shfl_sync(0xffffffffu, myidx, e + 3);
                float4 q0 = g_ax4[s0];
                float4 q1 = g_ax4[s1];
                float4 q2 = g_ax4[s2];
                float4 q3 = g_ax4[s3];
                float h;
                h = fmaxf(fmaf(q0.x, w1x0, fmaf(q0.y, w1y0, bb0)), 0.f); a0 = fmaf(q0.z, h, a0);
                h = fmaxf(fmaf(q0.x, w1x1, fmaf(q0.y, w1y1, bb1)), 0.f); a1 = fmaf(q0.z, h, a1);
                h = fmaxf(fmaf(q1.x, w1x0, fmaf(q1.y, w1y0, bb0)), 0.f); a0 = fmaf(q1.z, h, a0);
                h = fmaxf(fmaf(q1.x, w1x1, fmaf(q1.y, w1y1, bb1)), 0.f); a1 = fmaf(q1.z, h, a1);
                h = fmaxf(fmaf(q2.x, w1x0, fmaf(q2.y, w1y0, bb0)), 0.f); a0 = fmaf(q2.z, h, a0);
                h = fmaxf(fmaf(q2.x, w1x1, fmaf(q2.y, w1y1, bb1)), 0.f); a1 = fmaf(q2.z, h, a1);
                h = fmaxf(fmaf(q3.x, w1x0, fmaf(q3.y, w1y0, bb0)), 0.f); a0 = fmaf(q3.z, h, a0);
                h = fmaxf(fmaf(q3.x, w1x1, fmaf(q3.y, w1y1, bb1)), 0.f); a1 = fmaf(q3.z, h, a1);
            }
            for (; e < cnt; e++) {
                int s0 = __shfl_sync(0xffffffffu, myidx, e);
                float4 q0 = g_ax4[s0];
                float h;
                h = fmaxf(fmaf(q0.x, w1x0, fmaf(q0.y, w1y0, bb0)), 0.f); a0 = fmaf(q0.z, h, a0);
                h = fmaxf(fmaf(q0.x, w1x1, fmaf(q0.y, w1y1, bb1)), 0.f); a1 = fmaf(q0.z, h, a1);
            }
        }
        float4 q = g_ax4[v];            // self term
        float h;
        h = fmaxf(fmaf(q.x, w1x0, fmaf(q.y, w1y0, bb0)), 0.f); a0 = fmaf(q.z, h, a0);
        h = fmaxf(fmaf(q.x, w1x1, fmaf(q.y, w1y1, bb1)), 0.f); a1 = fmaf(q.z, h, a1);
        a0 *= q.z;
        a1 *= q.z;
    }
    sT[lane * 9 + wid] = a0;
    sT[(lane + 32) * 9 + wid] = a1;
    __syncthreads();
    if (t < 64) {
        int j = t >> 3, ch = t & 7;
        int v2 = blockIdx.x * 8 + j;
        if (v2 < n) {
            int tile = v2 >> 7, r = v2 & 127;
            uint4 u;
            u.x = bf16pack(sT[(ch*8+0)*9 + j], sT[(ch*8+1)*9 + j]);
            u.y = bf16pack(sT[(ch*8+2)*9 + j], sT[(ch*8+3)*9 + j]);
            u.z = bf16pack(sT[(ch*8+4)*9 + j], sT[(ch*8+5)*9 + j]);
            u.w = bf16pack(sT[(ch*8+6)*9 + j], sT[(ch*8+7)*9 + j]);
            *(uint4*)(g_bf + (size_t)tile * 16384 + r * 128 + ch * 16) = u;
        }
    }
}

// ---------------- mma.sync MLP (R14-validated) ----------------
__global__ __launch_bounds__(256, 2) void k_mlp(const float* __restrict__ W2,
                                                const float* __restrict__ b2,
                                                const float* __restrict__ W3,
                                                int n) {
    extern __shared__ char sm[];
    u64*  bfr = (u64*)sm;                  // [4][4][8][32] weight fragments, 32KB
    char* At  = sm + 32768;                // A tile: 128 x 144B
    const int t = threadIdx.x, lane = t & 31, w = t >> 5;

    for (int fg = w; fg < 128; fg += 8) {
        int v  = fg >> 5;
        int ks = (fg >> 3) & 3;
        int nb = fg & 7;
        const float* W = (v < 2) ? W2 : W3;
        int nn = nb * 8 + (lane >> 2);
        int k0 = ks * 16 + (lane & 3) * 2;
        float w00 = __ldg(&W[k0 * 64 + nn]);
        float w01 = __ldg(&W[(k0 + 1) * 64 + nn]);
        float w08 = __ldg(&W[(k0 + 8) * 64 + nn]);
        float w09 = __ldg(&W[(k0 + 9) * 64 + nn]);
        unsigned b0, b1;
        if (v & 1) {
            b0 = bf16pack(bf16resid(w00), bf16resid(w01));
            b1 = bf16pack(bf16resid(w08), bf16resid(w09));
        } else {
            b0 = bf16pack(w00, w01);
            b1 = bf16pack(w08, w09);
        }
        bfr[fg * 32 + lane] = ((u64)b1 << 32) | (u64)b0;
    }
    float2 b2p[8];
    #pragma unroll
    for (int nb = 0; nb < 8; nb++) {
        int c = nb * 8 + (lane & 3) * 2;
        b2p[nb] = make_float2(__ldg(&b2[c]), __ldg(&b2[c + 1]));
    }
    __syncthreads();

    const uint32_t at_base = smem_u32(At);
    const int ntiles = (n + 127) >> 7;
    for (int tile = blockIdx.x; tile < ntiles; tile += gridDim.x) {
        const int base = tile << 7;
        for (int q = t; q < 1024; q += 256) {
            int r = q >> 3, p = q & 7;
            uint4 val = *(const uint4*)(g_bf + (size_t)tile * 16384 + r * 128 + p * 16);
            *(uint4*)(At + r * 144 + p * 16) = val;
        }
        __syncthreads();

        unsigned aF[4][4];
        uint32_t arow = at_base + (w * 16 + (lane & 15)) * 144 + (lane >> 4) * 16;
        #pragma unroll
        for (int ks = 0; ks < 4; ks++) ldmatrix4(aF[ks], arow + ks * 32);
        __syncthreads();

        float acc[8][4];
        #pragma unroll
        for (int nb = 0; nb < 8; nb++)
            #pragma unroll
            for (int i = 0; i < 4; i++) acc[nb][i] = 0.f;
        #pragma unroll
        for (int ks = 0; ks < 4; ks++) {
            #pragma unroll
            for (int nb = 0; nb < 8; nb++) {
                u64 fh = bfr[((0 * 4 + ks) * 8 + nb) * 32 + lane];
                mma_bf16(acc[nb], aF[ks], (unsigned)fh, (unsigned)(fh >> 32));
                u64 fl = bfr[((1 * 4 + ks) * 8 + nb) * 32 + lane];
                mma_bf16(acc[nb], aF[ks], (unsigned)fl, (unsigned)(fl >> 32));
            }
        }

        unsigned a2[4][4];
        #pragma unroll
        for (int j = 0; j < 4; j++) {
            int n0 = 2 * j, n1 = 2 * j + 1;
            a2[j][0] = bf16pack(fmaxf(acc[n0][0] + b2p[n0].x, 0.f),
                                fmaxf(acc[n0][1] + b2p[n0].y, 0.f));
            a2[j][1] = bf16pack(fmaxf(acc[n0][2] + b2p[n0].x, 0.f),
                                fmaxf(acc[n0][3] + b2p[n0].y, 0.f));
            a2[j][2] = bf16pack(fmaxf(acc[n1][0] + b2p[n1].x, 0.f),
                                fmaxf(acc[n1][1] + b2p[n1].y, 0.f));
            a2[j][3] = bf16pack(fmaxf(acc[n1][2] + b2p[n1].x, 0.f),
                                fmaxf(acc[n1][3] + b2p[n1].y, 0.f));
        }

        float acc2[8][4];
        #pragma unroll
        for (int nb = 0; nb < 8; nb++)
            #pragma unroll
            for (int i = 0; i < 4; i++) acc2[nb][i] = 0.f;
        #pragma unroll
        for (int ks = 0; ks < 4; ks++) {
            #pragma unroll
            for (int nb = 0; nb < 8; nb++) {
                u64 fh = bfr[((2 * 4 + ks) * 8 + nb) * 32 + lane];
                mma_bf16(acc2[nb], a2[ks], (unsigned)fh, (unsigned)(fh >> 32));
                u64 fl = bfr[((3 * 4 + ks) * 8 + nb) * 32 + lane];
                mma_bf16(acc2[nb], a2[ks], (unsigned)fl, (unsigned)(fl >> 32));
            }
        }

        int r0 = base + w * 16 + (lane >> 2);
        int r1 = r0 + 8;
        float dv0 = (r0 < n) ? __ldg(&g_dinv[r0]) : 0.f;
        float dv1 = (r1 < n) ? __ldg(&g_dinv[r1]) : 0.f;
        int coff = (lane & 3) * 2;
        #pragma unroll
        for (int nb = 0; nb < 8; nb++) {
            unsigned short v0 = fp8pack2(acc2[nb][0] * dv0, acc2[nb][1] * dv0);
            unsigned short v1 = fp8pack2(acc2[nb][2] * dv1, acc2[nb][3] * dv1);
            if (r0 < n) *(unsigned short*)(g_buf8 + (size_t)r0 * 64 + nb * 8 + coff) = v0;
            if (r1 < n) *(unsigned short*)(g_buf8 + (size_t)r1 * 64 + nb * 8 + coff) = v1;
        }
    }
}

// ---------------- layer 3 aggregation: shfl-broadcast indices (warp-uniform) -----
// warp per node; indices prefetched lane-parallel; half-warps process edges
// e+0 / e+1 per iteration (2 independent gathers in flight warp-wide).
__global__ void k_agg64(const float* __restrict__ b3, int n) {
    int t = threadIdx.x;
    int w = (blockIdx.x * blockDim.x + t) >> 5;
    int lane = t & 31;
    int half = lane >> 4, l16 = lane & 15;
    if (w >= n) return;
    int st = g_off[w];
    int deg = g_off[w + 1] - st;
    float4 a = make_float4(0.f, 0.f, 0.f, 0.f);
    for (int base = 0; base < deg; base += 32) {
        int li = base + lane;
        int myidx = (li < deg) ? __ldg(&g_csrc[st + li]) : 0;
        int cnt = min(32, deg - base);
        for (int e = 0; e < cnt; e += 2) {          // warp-uniform trip count
            int idx = e + half;                      // half in {0,1}
            int s = __shfl_sync(0xffffffffu, myidx, (idx < cnt) ? idx : 0);
            if (idx < cnt) {
                unsigned u = *(const unsigned*)(g_buf8 + (size_t)s * 64 + l16 * 4);
                float2 f01 = fp8unpack2((unsigned short)(u & 0xffffu));
                float2 f23 = fp8unpack2((unsigned short)(u >> 16));
                a.x += f01.x; a.y += f01.y; a.z += f23.x; a.w += f23.y;
            }
        }
    }
    if (half == 0) {
        unsigned u = *(const unsigned*)(g_buf8 + (size_t)w * 64 + l16 * 4);   // self
        float2 f01 = fp8unpack2((unsigned short)(u & 0xffffu));
        float2 f23 = fp8unpack2((unsigned short)(u >> 16));
        a.x += f01.x; a.y += f01.y; a.z += f23.x; a.w += f23.y;
    }
    a.x += __shfl_xor_sync(0xffffffffu, a.x, 16);
    a.y += __shfl_xor_sync(0xffffffffu, a.y, 16);
    a.z += __shfl_xor_sync(0xffffffffu, a.z, 16);
    a.w += __shfl_xor_sync(0xffffffffu, a.w, 16);
    if (half == 0) {
        float dv = g_dinv[w];
        float4 bb = *(const float4*)(b3 + l16 * 4);
        a.x = fmaf(dv, a.x, bb.x); a.y = fmaf(dv, a.y, bb.y);
        a.z = fmaf(dv, a.z, bb.z); a.w = fmaf(dv, a.w, bb.w);
        *(float4*)(g_h3 + (size_t)w * 64 + l16 * 4) = a;
    }
}

// ---------------- mean pool + head ----------------
__global__ void k_poolfinal(const int* __restrict__ batch, const float* __restrict__ ge,
                            const float* __restrict__ Wl, const float* __restrict__ bl,
                            float* __restrict__ out, int n) {
    __shared__ int sb[2];
    __shared__ float red[256];
    __shared__ int s_last;
    int gid = blockIdx.x;
    int t = threadIdx.x;
    if (t < 2) {
        int target = gid + t;
        int lo = 0, hi = n;
        while (lo < hi) {
            int mid = (lo + hi) >> 1;
            if (batch[mid] < target) lo = mid + 1; else hi = mid;
        }
        sb[t] = lo;
    }
    __syncthreads();
    int s = sb[0], e = sb[1];
    int d = t & 63, str = t >> 6;
    float acc = 0.f;
    for (int nn = s + str; nn < e; nn += 4) acc += g_h3[(size_t)nn * 64 + d];
    red[t] = acc;
    __syncthreads();
    if (t < 64) {
        float tot = red[t] + red[t + 64] + red[t + 128] + red[t + 192];
        g_pooled[gid * 64 + t] = tot / fmaxf((float)(e - s), 1.f);
    }
    __threadfence();
    if (t == 0) s_last = (atomicAdd(&g_poolctr, 1) == NGRAPH - 1);
    __syncthreads();
    if (!s_last) return;

    if (t == 0) g_poolctr = 0;
    __shared__ float sW[128 * NCLS];
    __shared__ float sbv[NCLS];
    for (int i = t; i < 128 * NCLS; i += 256) sW[i] = Wl[i];
    if (t < NCLS) sbv[t] = bl[t];
    __syncthreads();
    if (t < 128) {
        int g = t;
        float z[NCLS];
        #pragma unroll
        for (int c = 0; c < NCLS; c++) z[c] = sbv[c];
        for (int k = 0; k < 64; k++) {
            float p = g_pooled[g * HDIM + k];
            #pragma unroll
            for (int c = 0; c < NCLS; c++) z[c] = fmaf(p, sW[k * NCLS + c], z[c]);
        }
        for (int k = 0; k < 64; k++) {
            float p = ge[g * 64 + k];
            #pragma unroll
            for (int c = 0; c < NCLS; c++) z[c] = fmaf(p, sW[(64 + k) * NCLS + c], z[c]);
        }
        float m = z[0];
        #pragma unroll
        for (int c = 1; c < NCLS; c++) m = fmaxf(m, z[c]);
        float sum = 0.f;
        #pragma unroll
        for (int c = 0; c < NCLS; c++) sum += expf(z[c] - m);
        float l = m + logf(sum);
        #pragma unroll
        for (int c = 0; c < NCLS; c++) out[g * NCLS + c] = z[c] - l;
    }
}

// ---------------- launch ----------------
extern "C" void kernel_launch(void* const* d_in, const int* in_sizes, int n_in,
                              void* d_out, int out_size) {
    const float* x     = (const float*)d_in[0];
    const int*   ei    = (const int*)d_in[1];
    const int*   batch = (const int*)d_in[2];
    const float* ge    = (const float*)d_in[3];
    const float* W1    = (const float*)d_in[4];
    const float* b1    = (const float*)d_in[5];
    const float* W2    = (const float*)d_in[6];
    const float* b2    = (const float*)d_in[7];
    const float* W3    = (const float*)d_in[8];
    const float* b3    = (const float*)d_in[9];
    const float* Wl    = (const float*)d_in[10];
    const float* bl    = (const float*)d_in[11];
    float* out = (float*)d_out;

    int n  = in_sizes[0] / 2;
    int e  = in_sizes[1] / 2;
    int nb = (n + 1023) / 1024;

    static const int mlp_smem = 32768 + 128 * 144;   // 51200 B
    cudaFuncSetAttribute(k_mlp, cudaFuncAttributeMaxDynamicSharedMemorySize, mlp_smem);

    if ((e & 3) == 0)
        k_count4<<<((e >> 2) + 255) / 256, 256>>>(ei + e, e);    // 0
    else
        k_count1<<<(e + 255) / 256, 256>>>(ei + e, e);
    k_scan   <<<nb, 1024>>>(x, n);                               // 1
    if ((e & 3) == 0)
        k_scatter4<<<((e >> 2) + 255) / 256, 256>>>(ei, e);      // 2
    else
        k_scatter1<<<(e + 255) / 256, 256>>>(ei, e);
    k_agg2   <<<(2 * n + 255) / 256, 256>>>(n);                  // 3
    k_l2agg  <<<(n + 7) / 8, 256>>>(W1, b1, n);                  // 4
    k_mlp    <<<296, 256, mlp_smem>>>(W2, b2, W3, n);            // 5
    k_agg64  <<<(n + 7) / 8, 256>>>(b3, n);                      // 6
    k_poolfinal<<<NGRAPH, 256>>>(batch, ge, Wl, bl, out, n);     // 7
}